// round 7
// baseline (speedup 1.0000x reference)
#include <cuda_runtime.h>
#include <cuda_bf16.h>
#include <cstdint>

// OverlapPatchEmbed: x[64,3,224,224] -> out[64,729,3,256] (fp32)
// out[b, py*27+px, c, ky*16+kx] = x[b, c, py*8+ky, px*8+kx]
//
// R5: TMA bulk stores. Block = (py, pt, b), pt selects px in [9pt, 9pt+9).
//  1) stage input window (3ch x 16 rows x 80 floats = 15.4KB) into SMEM
//  2) build the block's contiguous 27,648B output region in SMEM
//  3) single cp.async.bulk (shared->global) store: no per-16B STG issue cost.
// Width 80 floats (mod 32 == 16) makes emit LDS conflict-free unpadded.

#define W4C    56                  // float4 per input row
#define SIN4   (3 * 16 * 20)       // 960 float4 staged  (20 f4 = 80 floats wide)
#define SOUT4  (9 * 3 * 64)        // 1728 float4 emitted (27,648 B)
#define NT     256

__global__ __launch_bounds__(NT) void overlap_patch_kernel(
    const float4* __restrict__ x, float4* __restrict__ out)
{
    __shared__ float4 s_in[SIN4];          // 15,360 B
    __shared__ float4 s_out[SOUT4];        // 27,648 B

    const int py  = blockIdx.x;
    const int pt  = blockIdx.y;            // px third: px = 9*pt + pxl
    const int b   = blockIdx.z;
    const int tid = threadIdx.x;

    // ---- stage: 3 ch x 16 rows x 20 float4, from col float 72*pt ----
    const long g0 = ((long)(b * 3) * 224 + py * 8) * W4C + 18 * pt;
    #pragma unroll
    for (int k = 0; k < 4; k++) {
        int i = tid + k * NT;
        if (i < SIN4) {
            int ch  = i / 320;             // 320 f4 per channel
            int r   = i - ch * 320;
            int row = r / 20;
            int col = r - row * 20;
            s_in[i] = x[g0 + (long)ch * (224 * W4C) + (long)row * W4C + col];
        }
    }
    __syncthreads();

    // ---- emit into SMEM: s_out index == global output offset within block ----
    const float* sf = reinterpret_cast<const float*>(s_in);
    #pragma unroll
    for (int k = 0; k < 7; k++) {
        int i = tid + k * NT;
        if (i < SOUT4) {
            int kx4 = i & 3;
            int ky  = (i >> 2) & 15;
            int t   = i >> 6;              // pxl*3 + c
            int c   = t % 3;
            int pxl = t / 3;
            // s_in float addr: c*1280 + ky*80 + pxl*8 + kx4*4 (16B aligned)
            s_out[i] = *reinterpret_cast<const float4*>(
                sf + c * 1280 + ky * 80 + pxl * 8 + (kx4 << 2));
        }
    }
    __syncthreads();

    // ---- bulk store: 27,648 contiguous bytes, one TMA op ----
    if (tid == 0) {
        asm volatile("fence.proxy.async.shared::cta;" ::: "memory");
        uint32_t saddr = (uint32_t)__cvta_generic_to_shared(s_out);
        const long obase = (((long)b * 729 + py * 27 + pt * 9) * 3) * 64; // f4
        float4* dst = out + obase;
        unsigned sz = SOUT4 * 16;
        asm volatile(
            "cp.async.bulk.global.shared::cta.bulk_group [%0], [%1], %2;"
            :: "l"(dst), "r"(saddr), "r"(sz) : "memory");
        asm volatile("cp.async.bulk.commit_group;" ::: "memory");
        asm volatile("cp.async.bulk.wait_group 0;" ::: "memory");
    }
}

extern "C" void kernel_launch(void* const* d_in, const int* in_sizes, int n_in,
                              void* d_out, int out_size)
{
    const float4* x = (const float4*)d_in[0];
    float4* out = (float4*)d_out;
    dim3 grid(27, 3, 64);
    overlap_patch_kernel<<<grid, NT>>>(x, out);
}

// round 10
// speedup vs baseline: 1.1089x; 1.1089x over previous
#include <cuda_runtime.h>
#include <cuda_bf16.h>
#include <cstdint>

// OverlapPatchEmbed: x[64,3,224,224] -> out[64,729,3,256] (fp32)
// out[b, py*27+px, c, ky*16+kx] = x[b, c, py*8+ky, px*8+kx]
//
// R8: persistent blocks + cp.async double-buffered pipeline.
// grid=864, 6 tiles/block (tile = (b,c,py), 16 full input rows = one
// contiguous 14336B span). Stage tile t+1 via cp.async.cg into padded SMEM
// while emitting tile t with conflict-free LDS.128 + coalesced STG.128.

#define NT      256
#define W4C     56                  // float4 per input row
#define PAD4    60                  // float4 per padded smem row
#define PADF    240
#define TIN4    (16 * W4C)          // 896 float4 staged per tile
#define BUF4    (16 * PAD4)         // 960 float4 per buffer
#define EMIT4   (27 * 64)           // 1728 float4 emitted per tile
#define NTILES  6                   // per block; 864*6 = 5184 tiles

__device__ __forceinline__ void stage_tile(
    const float4* __restrict__ x, float4* __restrict__ buf, int tile, int tid)
{
    int py = tile % 27;
    int q  = tile / 27;
    int c  = q % 3;
    int b  = q / 3;
    const float4* src = x + ((long)(b * 3 + c) * 224 + py * 8) * W4C;

    #pragma unroll
    for (int k = 0; k < 4; k++) {
        int i = tid + k * NT;
        if (i < TIN4) {
            int row = i / W4C;
            int col = i - row * W4C;
            uint32_t d = (uint32_t)__cvta_generic_to_shared(buf + row * PAD4 + col);
            asm volatile("cp.async.cg.shared.global [%0], [%1], 16;"
                         :: "r"(d), "l"(src + i) : "memory");
        }
    }
    asm volatile("cp.async.commit_group;" ::: "memory");
}

__global__ __launch_bounds__(NT) void overlap_patch_kernel(
    const float4* __restrict__ x, float4* __restrict__ out)
{
    __shared__ float4 buf[2][BUF4];          // 2 x 15360 B

    const int g   = blockIdx.x;
    const int tid = threadIdx.x;
    const int t0  = g * NTILES;

    stage_tile(x, buf[0], t0, tid);

    #pragma unroll
    for (int t = 0; t < NTILES; t++) {
        if (t + 1 < NTILES) {
            stage_tile(x, buf[(t + 1) & 1], t0 + t + 1, tid);
            asm volatile("cp.async.wait_group 1;" ::: "memory");
        } else {
            asm volatile("cp.async.wait_group 0;" ::: "memory");
        }
        __syncthreads();

        // ---- emit tile t ----
        int tile = t0 + t;
        int py = tile % 27;
        int q  = tile / 27;
        int c  = q % 3;
        int b  = q / 3;
        float4* __restrict__ o = out + (((long)b * 729 + py * 27) * 3 + c) * 64;
        const float* sf = reinterpret_cast<const float*>(buf[t & 1]);

        #pragma unroll
        for (int k = 0; k < 7; k++) {
            int i = tid + k * NT;
            if (i < EMIT4) {
                int kx4 = i & 3;
                int ky  = (i >> 2) & 15;
                int px  = i >> 6;
                float4 v = *reinterpret_cast<const float4*>(
                    sf + ky * PADF + px * 8 + (kx4 << 2));
                o[px * 192 + (ky << 2) + kx4] = v;
            }
        }
        __syncthreads();   // emit done before buf[t&1] is restaged next iter
    }
}

extern "C" void kernel_launch(void* const* d_in, const int* in_sizes, int n_in,
                              void* d_out, int out_size)
{
    const float4* x = (const float4*)d_in[0];
    float4* out = (float4*)d_out;
    overlap_patch_kernel<<<864, NT>>>(x, out);
}

// round 11
// speedup vs baseline: 1.2020x; 1.0839x over previous
#include <cuda_runtime.h>
#include <cuda_bf16.h>

// OverlapPatchEmbed: x[64,3,224,224] -> out[64,729,3,256] (fp32)
// out[b, py*27+px, c, ky*16+kx] = x[b, c, py*8+ky, px*8+kx]
//
// R11: R3 scheme + 3 consecutive py per block. Block = (pg, c, b) stages 32
// contiguous input rows (one linear 28,672B span) into padded SMEM once, then
// emits 3 overlapping patch-rows (py = 3*pg + dpy). Cuts L2 read traffic 34%
// vs 16-row tiles (shared rows staged once). Emit LDS.128 conflict-free
// (row pitch 240 floats), stores remain linear STG.128.

#define NT      512
#define W4C     56                  // float4 per input row
#define PAD4    60                  // float4 per padded smem row
#define PADF    240
#define ROWS_   32                  // 3*8 + 16 = 32 rows staged
#define TIN4    (ROWS_ * W4C)       // 1792 float4 staged
#define EMIT4   (3 * 27 * 64)       // 5184 float4 emitted

__global__ __launch_bounds__(NT) void overlap_patch_kernel(
    const float4* __restrict__ x, float4* __restrict__ out)
{
    __shared__ float4 s[ROWS_ * PAD4];        // 30,720 B

    const int pg  = blockIdx.x;               // py group: py = 3*pg + dpy
    const int c   = blockIdx.y;
    const int b   = blockIdx.z;
    const int tid = threadIdx.x;

    // ---- stage: 32 contiguous rows, linear coalesced LDG.128 ----
    const float4* src = x + ((long)(b * 3 + c) * 224 + pg * 24) * W4C;
    #pragma unroll
    for (int k = 0; k < 3; k++) {
        int i = tid + k * NT;
        int row = i / W4C;
        int col = i - row * W4C;
        s[row * PAD4 + col] = src[i];
    }
    {
        int i = tid + 3 * NT;                 // tail: 1792 - 1536 = 256
        if (i < TIN4) {
            int row = i / W4C;
            int col = i - row * W4C;
            s[row * PAD4 + col] = src[i];
        }
    }
    __syncthreads();

    // ---- emit: 3 patch-rows x 27 patches x 64 float4 ----
    const long obase = (((long)b * 729 + pg * 81) * 3 + c) * 64;
    float4* __restrict__ o = out + obase;
    const float* sf = reinterpret_cast<const float*>(s);

    #pragma unroll
    for (int k = 0; k < 11; k++) {
        int i = tid + k * NT;
        if (i < EMIT4) {
            int dpy = i / 1728;
            int j   = i - dpy * 1728;
            int kx4 = j & 3;
            int ky  = (j >> 2) & 15;
            int px  = j >> 6;
            // smem float addr: (dpy*8+ky)*240 + px*8 + kx4*4  (16B aligned)
            float4 v = *reinterpret_cast<const float4*>(
                sf + (dpy * 8 + ky) * PADF + px * 8 + (kx4 << 2));
            // out f4 offset: dpy*27*192 + px*192 + ky*4 + kx4
            o[dpy * 5184 + px * 192 + (ky << 2) + kx4] = v;
        }
    }
}

extern "C" void kernel_launch(void* const* d_in, const int* in_sizes, int n_in,
                              void* d_out, int out_size)
{
    const float4* x = (const float4*)d_in[0];
    float4* out = (float4*)d_out;
    dim3 grid(9, 3, 64);                      // 1728 blocks
    overlap_patch_kernel<<<grid, NT>>>(x, out);
}

// round 12
// speedup vs baseline: 1.2636x; 1.0513x over previous
#include <cuda_runtime.h>
#include <cuda_bf16.h>

// OverlapPatchEmbed: x[64,3,224,224] -> out[64,729,3,256] (fp32)
// out[b, py*27+px, c, ky*16+kx] = x[b, c, py*8+ky, px*8+kx]
//
// R12: R11 data plan (block = (pg,c,b), 32 contiguous rows staged once,
// 3 overlapping patch-rows emitted; padded SMEM pitch 240 floats ->
// conflict-free LDS.128; linear coalesced STG.128) with the emit index math
// hoisted: NT=512 == 0 mod 64 makes kx4/ky loop-invariant per thread, so the
// inner loop is LDS.128 + STG.128 + tiny patch-index update.

#define NT      512
#define W4C     56                  // float4 per input row
#define PAD4    60                  // float4 per padded smem row
#define PADF    240
#define ROWS_   32                  // 3 patch-rows: 3*8 + 8 = 32 rows staged
#define TIN4    (ROWS_ * W4C)       // 1792 float4 staged
#define NPATCH  81                  // 3 * 27 patches emitted per block

__global__ __launch_bounds__(NT) void overlap_patch_kernel(
    const float4* __restrict__ x, float4* __restrict__ out)
{
    __shared__ float4 s[ROWS_ * PAD4];        // 30,720 B

    const int pg  = blockIdx.x;               // py = 3*pg + dpy
    const int c   = blockIdx.y;
    const int b   = blockIdx.z;
    const int tid = threadIdx.x;

    // ---- stage: 32 contiguous rows, linear coalesced LDG.128 ----
    const float4* src = x + ((long)(b * 3 + c) * 224 + pg * 24) * W4C;
    #pragma unroll
    for (int k = 0; k < 3; k++) {
        int i = tid + k * NT;
        int row = i / W4C;
        int col = i - row * W4C;
        s[row * PAD4 + col] = src[i];
    }
    {
        int i = tid + 3 * NT;                 // tail: 1792 - 1536 = 256
        if (i < TIN4) {
            int row = i / W4C;
            int col = i - row * W4C;
            s[row * PAD4 + col] = src[i];
        }
    }
    __syncthreads();

    // ---- emit: 81 patches x 64 float4, hoisted per-thread invariants ----
    // thread -> (kx4, ky) fixed; p = patch index (dpy*27 + px) advances by 8.
    const int kx4 = tid & 3;
    const int ky  = (tid >> 2) & 15;
    const int p0  = tid >> 6;                 // 0..7

    const float* sbase = reinterpret_cast<const float*>(s)
                         + ky * PADF + (kx4 << 2);
    float4* __restrict__ obase =
        out + (((long)b * 729 + pg * 81) * 3 + c) * 64 + (ky << 2) + kx4;

    #pragma unroll
    for (int k = 0; k < 11; k++) {
        int p = p0 + (k << 3);
        if (p < NPATCH) {
            int dpy = (p * 1214) >> 15;       // p/27 for p in [0,81)
            int px  = p - dpy * 27;
            float4 v = *reinterpret_cast<const float4*>(
                sbase + dpy * (8 * PADF) + (px << 3));
            obase[dpy * 5184 + px * 192] = v;
        }
    }
}

extern "C" void kernel_launch(void* const* d_in, const int* in_sizes, int n_in,
                              void* d_out, int out_size)
{
    const float4* x = (const float4*)d_in[0];
    float4* out = (float4*)d_out;
    dim3 grid(9, 3, 64);                      // 1728 blocks
    overlap_patch_kernel<<<grid, NT>>>(x, out);
}